// round 9
// baseline (speedup 1.0000x reference)
#include <cuda_runtime.h>
#include <math.h>

// Problem constants
#define BATCH 2048
#define DIM   3072
#define NCLS  10
#define MDIM  9
#define TPB   512
#define NWARP 16
#define NPAIR 8
#define GRID  148
#define NTASK (BATCH / 2)      // 1024 tasks, 2 samples each
#define PAD   3084             // Wt row stride
#define SCALE 0.999999f
#define NSTAB 1e-7f
#define EPS2  0.01f

#define WT_BYTES (NCLS * PAD * 4)   // 123360

__device__ float        g_norm[BATCH];
__device__ unsigned int g_count;     // zero-init; reset in-kernel

// pair-private barrier: 2 warps, ids 1..8
__device__ __forceinline__ void pair_bar(int pair) {
    asm volatile("bar.sync %0, %1;" :: "r"(pair + 1), "r"(64) : "memory");
}

// ---------------------------------------------------------------------------
// Warp-pair fused kernel (TPB=512, 16 warps/SM):
//   each task (2 samples) owned by a warp pair; each warp covers half of DIM
//   for BOTH samples (W LDS amortized over 2 samples), pair combines logits
//   via smem + named barrier, then each warp runs ONE sample's epilogue.
// ---------------------------------------------------------------------------
__global__ void __launch_bounds__(TPB, 1)
k_fused(const float* __restrict__ data,
        const float* __restrict__ W,
        const float* __restrict__ b,
        float* __restrict__ out) {
    extern __shared__ float Wt[];                 // [NCLS][PAD]
    __shared__ float Gs[NCLS * NCLS];
    __shared__ float shop[NWARP][56];             // G staging
    __shared__ float scr[NPAIR][2][8][2][NCLS];   // pair, role, group, sample
    __shared__ float shp[NWARP][NCLS];
    __shared__ float sha[NWARP][MDIM];
    __shared__ float shb[NWARP][MDIM];
    __shared__ float shg[NWARP][NCLS];
    __shared__ float red[TPB];
    __shared__ unsigned int s_rank;

    const int tid  = threadIdx.x;
    const int lane = tid & 31;
    const int wid  = tid >> 5;
    const int pair = wid >> 1;
    const int role = wid & 1;

    // ---- stage 1: W -> Wt (transposed); 7680 float4 over 512 threads
    {
        const float4* W4 = (const float4*)W;
        int d = (4 * tid) / NCLS;
        int l = (4 * tid) % NCLS;
        for (int i = 0; i < 15; i++) {
            const float4 v = W4[tid + i * TPB];
            int dd = d, ll = l;
            Wt[ll * PAD + dd] = v.x;
            if (++ll == NCLS) { ll = 0; dd++; }
            Wt[ll * PAD + dd] = v.y;
            if (++ll == NCLS) { ll = 0; dd++; }
            Wt[ll * PAD + dd] = v.z;
            if (++ll == NCLS) { ll = 0; dd++; }
            Wt[ll * PAD + dd] = v.w;
            // advance e by 4*TPB = 2048 = 204*10 + 8
            d += 204; l += 8;
            if (l >= NCLS) { l -= NCLS; d++; }
        }
    }
    __syncthreads();

    // ---- stage 2: G = W^T W (upper triangle) from smem rows
    {
        float op[55];
        #pragma unroll
        for (int e = 0; e < 55; e++) op[e] = 0.f;
        #pragma unroll
        for (int i = 0; i < DIM / TPB; i++) {
            const int d = tid + i * TPB;
            float wrow[NCLS];
            #pragma unroll
            for (int l = 0; l < NCLS; l++) wrow[l] = Wt[l * PAD + d];
            int e = 0;
            #pragma unroll
            for (int i2 = 0; i2 < NCLS; i2++)
                #pragma unroll
                for (int j2 = i2; j2 < NCLS; j2++)
                    op[e++] += wrow[i2] * wrow[j2];
        }
        #pragma unroll
        for (int e = 0; e < 55; e++) {
            #pragma unroll
            for (int off = 16; off; off >>= 1)
                op[e] += __shfl_xor_sync(0xFFFFFFFFu, op[e], off);
        }
        if (lane == 0) {
            #pragma unroll
            for (int e = 0; e < 55; e++) shop[wid][e] = op[e];
        }
    }
    __syncthreads();
    if (tid < 55) {
        float t = 0.f;
        #pragma unroll
        for (int w = 0; w < NWARP; w++) t += shop[w][tid];
        int e = tid, i = 0;
        while (e >= NCLS - i) { e -= NCLS - i; i++; }
        const int j = i + e;
        Gs[i * NCLS + j] = t;
        Gs[j * NCLS + i] = t;
    }
    __syncthreads();

    // ---- main: warp-pair autonomous
    const int task = blockIdx.x + gridDim.x * pair;
    if (task < NTASK) {
        const float bl = (lane < NCLS) ? b[lane] : 0.f;
        // this warp's half of DIM: d4 in [role*384, role*384+384)
        const int d4base = role * 384 + lane;
        const float4* xp0 =
            (const float4*)(data + (size_t)(2 * task) * DIM) + d4base;
        const float4* xp1 = xp0 + DIM / 4;

        float acc0[NCLS], acc1[NCLS];
        #pragma unroll
        for (int l = 0; l < NCLS; l++) { acc0[l] = 0.f; acc1[l] = 0.f; }

        // 3 chunks x 4 float4 per sample (12 d4 per lane = 1536 dims/warp)
        float4 ba[2][4], bb[2][4];
        #pragma unroll
        for (int k = 0; k < 4; k++) {
            ba[0][k] = xp0[32 * k];
            bb[0][k] = xp1[32 * k];
        }
        #pragma unroll
        for (int c = 0; c < 3; c++) {
            const int cur = c & 1, nxt = cur ^ 1;
            if (c < 2) {
                #pragma unroll
                for (int k = 0; k < 4; k++) {
                    ba[nxt][k] = xp0[32 * (4 * (c + 1) + k)];
                    bb[nxt][k] = xp1[32 * (4 * (c + 1) + k)];
                }
            }
            #pragma unroll
            for (int k = 0; k < 4; k++) {
                const int d4 = d4base + 32 * (4 * c + k);
                const float4 xa = ba[cur][k];
                const float4 xb = bb[cur][k];
                #pragma unroll
                for (int l = 0; l < NCLS; l++) {
                    const float4 w = *(const float4*)(Wt + l * PAD + 4 * d4);
                    acc0[l] += xa.x * w.x + xa.y * w.y
                             + xa.z * w.z + xa.w * w.w;
                    acc1[l] += xb.x * w.x + xb.y * w.y
                             + xb.z * w.z + xb.w * w.w;
                }
            }
        }

        // 2-step butterfly -> lanes 0..7 hold 4-lane group sums
        #pragma unroll
        for (int l = 0; l < NCLS; l++) {
            #pragma unroll
            for (int off = 16; off >= 8; off >>= 1) {
                acc0[l] += __shfl_xor_sync(0xFFFFFFFFu, acc0[l], off);
                acc1[l] += __shfl_xor_sync(0xFFFFFFFFu, acc1[l], off);
            }
        }
        if (lane < 8) {
            #pragma unroll
            for (int l = 0; l < NCLS; l++) {
                scr[pair][role][lane][0][l] = acc0[l];
                scr[pair][role][lane][1][l] = acc1[l];
            }
        }
        pair_bar(pair);    // combine partials across the pair (drains STS)

        // ---- in-warp epilogue: warp `role` handles sample 2*task+role
        {
            float logit = -1e30f;
            if (lane < NCLS) {
                float v0 = bl, v1 = 0.f;
                #pragma unroll
                for (int g = 0; g < 8; g++) {
                    v0 += scr[pair][0][g][role][lane];
                    v1 += scr[pair][1][g][role][lane];
                }
                logit = v0 + v1;
            }
            // softmax over lanes 0..9 (16-lane butterfly; lanes 16..31 get
            // correct scalars via the factor broadcast below)
            float mval = logit;
            #pragma unroll
            for (int off = 8; off; off >>= 1)
                mval = fmaxf(mval, __shfl_xor_sync(0xFFFFFFFFu, mval, off));
            float e = (lane < NCLS) ? expf(logit - mval) : 0.f;
            float ssum = e;
            #pragma unroll
            for (int off = 8; off; off >>= 1)
                ssum += __shfl_xor_sync(0xFFFFFFFFu, ssum, off);
            const float p  = e / ssum;
            const float q  = p * SCALE + NSTAB;
            const float nc = sqrtf(q);
            float ncs = (lane < NCLS) ? nc : 0.f;
            #pragma unroll
            for (int off = 8; off; off >>= 1)
                ncs += __shfl_xor_sync(0xFFFFFFFFu, ncs, off);
            const float nc9 = __shfl_sync(0xFFFFFFFFu, nc, 9);
            const float p9  = __shfl_sync(0xFFFFFFFFu, p, 9);
            const float denom = 1.f - nc9;
            float arg = ncs * 0.3162277660168379f;   // 1/sqrt(10)
            arg = fminf(arg, 1.f);
            const float delta  = 2.f * acosf(arg);
            float factor = delta * delta / (4.f * denom * denom * EPS2);
            factor = __shfl_sync(0xFFFFFFFFu, factor, 0);

            if (lane < NCLS) shp[wid][lane] = p;
            if (lane < MDIM) {
                sha[wid][lane] = SCALE * p / (nc * denom);
                shb[wid][lane] = SCALE * nc * p9 / (nc9 * denom * denom);
            }
            __syncwarp();
            if (lane < NCLS) {
                float gg = 0.f;
                #pragma unroll
                for (int k2 = 0; k2 < NCLS; k2++)
                    gg += Gs[lane * NCLS + k2] * shp[wid][k2];
                shg[wid][lane] = gg;
            }
            __syncwarp();
            float sdot = 0.f;
            #pragma unroll
            for (int k2 = 0; k2 < NCLS; k2++)
                sdot += shp[wid][k2] * shg[wid][k2];
            const float tval = shg[wid][MDIM];
            const float r    = Gs[MDIM * NCLS + MDIM];

            // M = A G A^T via rank structure (81 entries over 32 lanes)
            float ssq = 0.f;
            #pragma unroll
            for (int rep = 0; rep < 3; rep++) {
                const int e2 = lane + rep * 32;
                if (e2 < MDIM * MDIM) {
                    const int i = e2 / MDIM, j = e2 % MDIM;
                    const float ai = sha[wid][i], aj = sha[wid][j];
                    const float bi = shb[wid][i], bj = shb[wid][j];
                    const float gi = -(ai + bi), gj = -(aj + bj);
                    const float ggi = shg[wid][i], ggj = shg[wid][j];
                    float Mij = ai * aj * Gs[i * NCLS + j]
                              + ai * bj * Gs[i * NCLS + MDIM]
                              + bi * aj * Gs[j * NCLS + MDIM]
                              + ai * gj * ggi
                              + gi * aj * ggj
                              + bi * bj * r
                              + (bi * gj + gi * bj) * tval
                              + gi * gj * sdot;
                    const float v2 = Mij - ((i == j) ? factor : 0.f);
                    ssq += v2 * v2;
                }
            }
            #pragma unroll
            for (int off = 16; off; off >>= 1)
                ssq += __shfl_xor_sync(0xFFFFFFFFu, ssq, off);
            if (lane == 0) g_norm[2 * task + role] = sqrtf(ssq);
        }
    }

    // ---- fused final reduction: last block to arrive does it
    __syncthreads();
    if (tid == 0) {
        __threadfence();
        s_rank = atomicAdd(&g_count, 1u);
    }
    __syncthreads();
    if (s_rank == GRID - 1) {
        __threadfence();
        float t0 = 0.f, t1 = 0.f;
        #pragma unroll
        for (int k = 0; k < BATCH / TPB; k += 2) {
            t0 += g_norm[tid + k * TPB];
            t1 += g_norm[tid + (k + 1) * TPB];
        }
        red[tid] = t0 + t1;
        __syncthreads();
        #pragma unroll
        for (int off = TPB / 2; off; off >>= 1) {
            if (tid < off) red[tid] += red[tid + off];
            __syncthreads();
        }
        if (tid == 0) {
            out[0] = red[0] * (1.0f / (BATCH * 81.0f));
            g_count = 0;
        }
    }
}

// ---------------------------------------------------------------------------
extern "C" void kernel_launch(void* const* d_in, const int* in_sizes, int n_in,
                              void* d_out, int out_size) {
    const float* data = 0;
    const float* W    = 0;
    const float* b    = 0;
    for (int i = 0; i < n_in; i++) {
        if (in_sizes[i] == BATCH * DIM)      data = (const float*)d_in[i];
        else if (in_sizes[i] == DIM * NCLS)  W    = (const float*)d_in[i];
        else if (in_sizes[i] == NCLS)        b    = (const float*)d_in[i];
    }
    float* out = (float*)d_out;

    cudaFuncSetAttribute(k_fused,
                         cudaFuncAttributeMaxDynamicSharedMemorySize,
                         WT_BYTES);
    k_fused<<<GRID, TPB, WT_BYTES>>>(data, W, b, out);
}